// round 4
// baseline (speedup 1.0000x reference)
#include <cuda_runtime.h>
#include <cstdint>
#include <math.h>

#define G_DIM   2304
#define HIDDEN  150
#define N_PAIRS 32768
#define N_MENT  4096
#define N_SEG   1024

#define TN 160
#define TK 32
#define NCHUNK (G_DIM / TK)   // 72
#define BPAD 168              // Bs row stride (words): 168 % 32 = 8 -> conflict-free

// ---------------- device scratch (static; no allocation) -------------------
__device__ float d_Wp[3 * G_DIM * TN];    // W1 sections tf32-rounded, [sec][k][160]
__device__ float d_Abuf[N_MENT * TN];     // g_i @ W1a  (stride 160, cols>=150 zero)
__device__ float d_Bbuf[N_MENT * TN];     // g_i @ W1b
__device__ float d_bias[3 * TN];          // phi@W1d + b1, padded 0
__device__ float d_scores[N_PAIRS];

__device__ __forceinline__ uint32_t f2tf32(float x) {
    uint32_t u;
    asm("cvt.rna.tf32.f32 %0, %1;" : "=r"(u) : "f"(x));
    return u;
}
__device__ __forceinline__ uint32_t smem_u32(const void* p) {
    uint32_t a;
    asm("{ .reg .u64 t; cvta.to.shared.u64 t, %1; cvt.u32.u64 %0, t; }"
        : "=r"(a) : "l"(p));
    return a;
}
__device__ __forceinline__ void cp_async16(uint32_t dst, const void* src) {
    asm volatile("cp.async.cg.shared.global [%0], [%1], 16;"
                 :: "r"(dst), "l"(src) : "memory");
}
__device__ __forceinline__ void cp_async_commit_wait() {
    asm volatile("cp.async.commit_group;" ::: "memory");
    asm volatile("cp.async.wait_group 0;" ::: "memory");
}

__device__ __forceinline__ void mma_tf32(float* d, const uint32_t* a,
                                         const uint32_t* b) {
    asm volatile(
        "mma.sync.aligned.m16n8k8.row.col.f32.tf32.tf32.f32 "
        "{%0,%1,%2,%3}, {%4,%5,%6,%7}, {%8,%9}, {%0,%1,%2,%3};"
        : "+f"(d[0]), "+f"(d[1]), "+f"(d[2]), "+f"(d[3])
        : "r"(a[0]), "r"(a[1]), "r"(a[2]), "r"(a[3]), "r"(b[0]), "r"(b[1]));
}

// ---------------------------------------------------------------------------
// Prep: W1 sections -> tf32-rounded, zero-padded to 160 cols. [sec][k][160]
// ---------------------------------------------------------------------------
__global__ void prep_w_kernel(const float* __restrict__ W1) {
    int idx = blockIdx.x * 256 + threadIdx.x;
    if (idx >= 3 * G_DIM * TN) return;
    int sec = idx / (G_DIM * TN);
    int r = idx - sec * (G_DIM * TN);
    int k = r / TN, h = r - k * TN;
    float v = 0.f;
    if (h < HIDDEN)
        v = __uint_as_float(f2tf32(W1[(size_t)(sec * G_DIM + k) * HIDDEN + h]));
    d_Wp[idx] = v;
}

// ---------------------------------------------------------------------------
// bias[s][h] = b1[h] + phi[s] @ W1d[:,h]; padded 0 to TN.
// ---------------------------------------------------------------------------
__global__ void bias_kernel(const float* __restrict__ spk,
                            const float* __restrict__ W1,
                            const float* __restrict__ b1) {
    const float* Wd = W1 + (size_t)(3 * G_DIM) * HIDDEN;
    for (int idx = threadIdx.x; idx < 3 * TN; idx += blockDim.x) {
        int s = idx / TN, h = idx % TN;
        float v = 0.f;
        if (h < HIDDEN) {
            v = b1[h];
            #pragma unroll
            for (int t = 0; t < 20; t++)
                v = fmaf(spk[s * 20 + t], Wd[(size_t)t * HIDDEN + h], v);
        }
        d_bias[idx] = v;
    }
}

// ---------------------------------------------------------------------------
// Unified tf32 mma.sync GEMM.
//   PAIR=false: out[sec=blockIdx.y] = g_i @ W1[sec] -> d_Abuf / d_Bbuf
//   PAIR=true : (i∘j)@W1c + fused MLP epilogue -> d_scores
// Warps: (WM x 2); warp tile 64x80 = 4 m16-tiles x 10 n8-tiles. TM = WM*64.
// A stored k-major transposed As_t[k][TM+8]; B via cp.async.
// ---------------------------------------------------------------------------
template<int WM, bool PAIR>
__global__ __launch_bounds__(WM * 64, 2)
void mma_kernel(const float* __restrict__ G,
                const int*   __restrict__ m_ids,
                const int*   __restrict__ a_ids,
                const int*   __restrict__ spk_lbl,
                const float* __restrict__ mscores,
                const float* __restrict__ W2,
                const float* __restrict__ b2) {
    constexpr int TM  = WM * 64;
    constexpr int THR = WM * 64;
    constexpr int ATS = TM + 8;          // As_t row stride (words)

    __shared__ float As_t[TK][ATS];
    __shared__ float Bs[TK][BPAD];
    __shared__ float srow[2][TM];
    __shared__ float bias_s[3 * TN];
    __shared__ float w2s[TN];

    const int tid = threadIdx.x;
    const int wid = tid >> 5, lane = tid & 31;
    const int gID = lane >> 2, tig = lane & 3;
    const int warp_m = wid % WM, warp_n = wid / WM;
    const int base = blockIdx.x * TM;

    for (int i = tid; i < TN; i += THR) w2s[i] = (i < HIDDEN) ? W2[i] : 0.f;
    for (int i = tid; i < 3 * TN; i += THR) bias_s[i] = d_bias[i];

    const float* Wp = d_Wp + (size_t)(PAIR ? 2 : blockIdx.y) * G_DIM * TN;

    // staging: one thread per A row
    const int row = tid;
    const float *rowI, *rowJ = nullptr;
    if (PAIR) {
        int ii = m_ids[base + row], jj = a_ids[base + row];
        rowI = G + (size_t)ii * G_DIM;
        rowJ = G + (size_t)jj * G_DIM;
    } else {
        rowI = G + (size_t)(base + row) * G_DIM;
    }

    float acc[4][10][4];
    #pragma unroll
    for (int a = 0; a < 4; a++)
        #pragma unroll
        for (int b = 0; b < 10; b++)
            #pragma unroll
            for (int c = 0; c < 4; c++) acc[a][b][c] = 0.f;

    const uint32_t bs_base = smem_u32(Bs);

    for (int ch = 0; ch < NCHUNK; ch++) {
        const int k0 = ch * TK;
        // ---- B tile via cp.async (overlaps with A staging below) ----
        #pragma unroll
        for (int it = 0; it < 1280 / THR; it++) {
            int u = tid + it * THR;            // float4 units: 0..1279
            int k = u / 40, hq = u - k * 40;
            cp_async16(bs_base + (uint32_t)(k * BPAD + hq * 4) * 4u,
                       Wp + (size_t)(k0 + k) * TN + hq * 4);
        }
        // ---- A tile: products (or raw rows), tf32-rounded, k-major ----
        #pragma unroll
        for (int q = 0; q < 8; q++) {
            float4 vi = *reinterpret_cast<const float4*>(rowI + k0 + q * 4);
            float4 w;
            if (PAIR) {
                float4 vj = *reinterpret_cast<const float4*>(rowJ + k0 + q * 4);
                w.x = __uint_as_float(f2tf32(vi.x * vj.x));
                w.y = __uint_as_float(f2tf32(vi.y * vj.y));
                w.z = __uint_as_float(f2tf32(vi.z * vj.z));
                w.w = __uint_as_float(f2tf32(vi.w * vj.w));
            } else {
                w.x = __uint_as_float(f2tf32(vi.x));
                w.y = __uint_as_float(f2tf32(vi.y));
                w.z = __uint_as_float(f2tf32(vi.z));
                w.w = __uint_as_float(f2tf32(vi.w));
            }
            As_t[q * 4 + 0][row] = w.x;
            As_t[q * 4 + 1][row] = w.y;
            As_t[q * 4 + 2][row] = w.z;
            As_t[q * 4 + 3][row] = w.w;
        }
        cp_async_commit_wait();
        __syncthreads();

        const uint32_t* Bu = reinterpret_cast<const uint32_t*>(Bs);
        const uint32_t* Au = reinterpret_cast<const uint32_t*>(As_t);
        #pragma unroll
        for (int ks = 0; ks < 4; ks++) {
            uint32_t af[4][4];
            #pragma unroll
            for (int tm = 0; tm < 4; tm++) {
                int m0 = warp_m * 64 + tm * 16 + gID;
                af[tm][0] = Au[(ks * 8 + tig) * ATS + m0];
                af[tm][1] = Au[(ks * 8 + tig) * ATS + m0 + 8];
                af[tm][2] = Au[(ks * 8 + tig + 4) * ATS + m0];
                af[tm][3] = Au[(ks * 8 + tig + 4) * ATS + m0 + 8];
            }
            #pragma unroll
            for (int tn = 0; tn < 10; tn++) {
                int col = warp_n * 80 + tn * 8 + gID;
                uint32_t bf[2];
                bf[0] = Bu[(ks * 8 + tig) * BPAD + col];
                bf[1] = Bu[(ks * 8 + 4 + tig) * BPAD + col];
                #pragma unroll
                for (int tm = 0; tm < 4; tm++)
                    mma_tf32(acc[tm][tn], af[tm], bf);
            }
        }
        __syncthreads();
    }

    // ---- epilogue ----
    if (PAIR) {
        #pragma unroll
        for (int tm = 0; tm < 4; tm++) {
            #pragma unroll
            for (int rh = 0; rh < 2; rh++) {
                const int lr = warp_m * 64 + tm * 16 + rh * 8 + gID;
                const int p = base + lr;
                const int ii = m_ids[p], jj = a_ids[p], sp = spk_lbl[p];
                const float* Ar = d_Abuf + (size_t)ii * TN;
                const float* Br = d_Bbuf + (size_t)jj * TN;
                const float* bi = bias_s + sp * TN;
                float part = 0.f;
                #pragma unroll
                for (int tn = 0; tn < 10; tn++) {
                    const int h = warp_n * 80 + tn * 8 + tig * 2;
                    float2 av = *reinterpret_cast<const float2*>(Ar + h);
                    float2 bv = *reinterpret_cast<const float2*>(Br + h);
                    float v0 = acc[tm][tn][rh * 2 + 0] + av.x + bv.x + bi[h];
                    float v1 = acc[tm][tn][rh * 2 + 1] + av.y + bv.y + bi[h + 1];
                    part = fmaf(fmaxf(v0, 0.f), w2s[h], part);
                    part = fmaf(fmaxf(v1, 0.f), w2s[h + 1], part);
                }
                part += __shfl_xor_sync(0xffffffffu, part, 1);
                part += __shfl_xor_sync(0xffffffffu, part, 2);
                if (tig == 0) srow[warp_n][lr] = part;
            }
        }
        __syncthreads();
        for (int r = tid; r < TM; r += THR) {
            const int p = base + r;
            d_scores[p] = srow[0][r] + srow[1][r]
                        + b2[0] + mscores[m_ids[p]] + mscores[a_ids[p]];
        }
    } else {
        float* out = (blockIdx.y == 0) ? d_Abuf : d_Bbuf;
        #pragma unroll
        for (int tm = 0; tm < 4; tm++) {
            #pragma unroll
            for (int rh = 0; rh < 2; rh++) {
                const int m = base + warp_m * 64 + tm * 16 + rh * 8 + gID;
                #pragma unroll
                for (int tn = 0; tn < 10; tn++) {
                    const int h = warp_n * 80 + tn * 8 + tig * 2;
                    float2 v = make_float2(acc[tm][tn][rh * 2 + 0],
                                           acc[tm][tn][rh * 2 + 1]);
                    *reinterpret_cast<float2*>(out + (size_t)m * TN + h) = v;
                }
            }
        }
    }
}

// ---------------------------------------------------------------------------
// Ragged softmax with epsilon logit 0. One block per segment (sorted ids).
// ---------------------------------------------------------------------------
__global__ void softmax_kernel(const int* __restrict__ seg_ids,
                               float* __restrict__ out) {
    const int s = blockIdx.x;
    __shared__ int sh_lo, sh_hi;
    __shared__ float red[128];

    if (threadIdx.x == 0) {
        int lo = 0, hi = N_PAIRS;
        while (lo < hi) { int mid = (lo + hi) >> 1; if (seg_ids[mid] < s) lo = mid + 1; else hi = mid; }
        sh_lo = lo;
        hi = N_PAIRS;
        while (lo < hi) { int mid = (lo + hi) >> 1; if (seg_ids[mid] < s + 1) lo = mid + 1; else hi = mid; }
        sh_hi = lo;
    }
    __syncthreads();
    const int lo = sh_lo, hi = sh_hi;

    float m = 0.f;
    for (int p = lo + threadIdx.x; p < hi; p += blockDim.x)
        m = fmaxf(m, d_scores[p]);
    red[threadIdx.x] = m;
    __syncthreads();
    for (int st = 64; st; st >>= 1) {
        if (threadIdx.x < st) red[threadIdx.x] = fmaxf(red[threadIdx.x], red[threadIdx.x + st]);
        __syncthreads();
    }
    m = red[0];
    __syncthreads();

    float sum = 0.f;
    for (int p = lo + threadIdx.x; p < hi; p += blockDim.x)
        sum += expf(d_scores[p] - m);
    red[threadIdx.x] = sum;
    __syncthreads();
    for (int st = 64; st; st >>= 1) {
        if (threadIdx.x < st) red[threadIdx.x] += red[threadIdx.x + st];
        __syncthreads();
    }
    const float eps_e = expf(-m);
    const float inv_denom = 1.f / (red[0] + eps_e);

    for (int p = lo + threadIdx.x; p < hi; p += blockDim.x)
        out[p] = expf(d_scores[p] - m) * inv_denom;
    if (threadIdx.x == 0)
        out[N_PAIRS + s] = eps_e * inv_denom;
}

// ---------------------------------------------------------------------------
extern "C" void kernel_launch(void* const* d_in, const int* in_sizes, int n_in,
                              void* d_out, int out_size) {
    const float* g_i            = (const float*)d_in[0];
    const float* mention_scores = (const float*)d_in[1];
    const float* speaker_embed  = (const float*)d_in[2];
    const float* W1             = (const float*)d_in[3];
    const float* b1             = (const float*)d_in[4];
    const float* W2             = (const float*)d_in[5];
    const float* b2             = (const float*)d_in[6];
    const int*   mention_ids    = (const int*)d_in[7];
    const int*   antecedent_ids = (const int*)d_in[8];
    const int*   speaker_labels = (const int*)d_in[9];
    const int*   segment_ids    = (const int*)d_in[10];
    float* out = (float*)d_out;

    prep_w_kernel<<<(3 * G_DIM * TN + 255) / 256, 256>>>(W1);
    bias_kernel<<<1, 256>>>(speaker_embed, W1, b1);
    // precompute A/B: TM=64 -> 64 M-tiles x 2 sections = 128 CTAs (1 wave)
    mma_kernel<1, false><<<dim3(N_MENT / 64, 2), 64>>>(
        g_i, mention_ids, antecedent_ids, speaker_labels, mention_scores, W2, b2);
    // pair bilinear + fused epilogue: TM=128 -> 256 CTAs (1 wave at 2/SM)
    mma_kernel<2, true><<<dim3(N_PAIRS / 128, 1), 128>>>(
        g_i, mention_ids, antecedent_ids, speaker_labels, mention_scores, W2, b2);
    softmax_kernel<<<N_SEG, 128>>>(segment_ids, out);
}

// round 5
// speedup vs baseline: 1.4303x; 1.4303x over previous
#include <cuda_runtime.h>
#include <cstdint>
#include <math.h>

#define G_DIM   2304
#define HIDDEN  150
#define N_PAIRS 32768
#define N_MENT  4096
#define N_SEG   1024

#define TM 128
#define TN 160
#define TK 16
#define NCH_ALL (G_DIM / TK)     // 144
#define KSPLIT  4
#define NCH_PRE (NCH_ALL / KSPLIT)  // 36

#define APAD 20    // As row stride (words)
#define BPAD 168   // Bs row stride (words)

// ---------------- device scratch (static; no allocation) -------------------
__device__ float d_Wp[3 * G_DIM * TN];        // W1 sections tf32-rounded [sec][k][160]
__device__ float d_part[KSPLIT][2][N_MENT * TN];  // precompute partials
__device__ float d_Abuf[N_MENT * TN];         // g_i @ W1a
__device__ float d_Bbuf[N_MENT * TN];         // g_i @ W1b
__device__ float d_bias[3 * TN];
__device__ float d_scores[N_PAIRS];

__device__ __forceinline__ uint32_t f2tf32(float x) {
    uint32_t u;
    asm("cvt.rna.tf32.f32 %0, %1;" : "=r"(u) : "f"(x));
    return u;
}
__device__ __forceinline__ uint32_t smem_u32(const void* p) {
    uint32_t a;
    asm("{ .reg .u64 t; cvta.to.shared.u64 t, %1; cvt.u32.u64 %0, t; }"
        : "=r"(a) : "l"(p));
    return a;
}
__device__ __forceinline__ void cp_async16(uint32_t dst, const void* src) {
    asm volatile("cp.async.cg.shared.global [%0], [%1], 16;"
                 :: "r"(dst), "l"(src) : "memory");
}

__device__ __forceinline__ void mma_tf32(float* d, const uint32_t* a,
                                         const uint32_t* b) {
    asm volatile(
        "mma.sync.aligned.m16n8k8.row.col.f32.tf32.tf32.f32 "
        "{%0,%1,%2,%3}, {%4,%5,%6,%7}, {%8,%9}, {%0,%1,%2,%3};"
        : "+f"(d[0]), "+f"(d[1]), "+f"(d[2]), "+f"(d[3])
        : "r"(a[0]), "r"(a[1]), "r"(a[2]), "r"(a[3]), "r"(b[0]), "r"(b[1]));
}

// ---------------------------------------------------------------------------
__global__ void prep_w_kernel(const float* __restrict__ W1) {
    int idx = blockIdx.x * 256 + threadIdx.x;
    if (idx >= 3 * G_DIM * TN) return;
    int sec = idx / (G_DIM * TN);
    int r = idx - sec * (G_DIM * TN);
    int k = r / TN, h = r - k * TN;
    float v = 0.f;
    if (h < HIDDEN)
        v = __uint_as_float(f2tf32(W1[(size_t)(sec * G_DIM + k) * HIDDEN + h]));
    d_Wp[idx] = v;
}

__global__ void bias_kernel(const float* __restrict__ spk,
                            const float* __restrict__ W1,
                            const float* __restrict__ b1) {
    const float* Wd = W1 + (size_t)(3 * G_DIM) * HIDDEN;
    for (int idx = threadIdx.x; idx < 3 * TN; idx += blockDim.x) {
        int s = idx / TN, h = idx % TN;
        float v = 0.f;
        if (h < HIDDEN) {
            v = b1[h];
            #pragma unroll
            for (int t = 0; t < 20; t++)
                v = fmaf(spk[s * 20 + t], Wd[(size_t)t * HIDDEN + h], v);
        }
        d_bias[idx] = v;
    }
}

// ---------------------------------------------------------------------------
// Pipelined tf32 mma.sync GEMM. 256 thr = 8 warps (2 M x 4 N), warp tile 64x40.
//   PAIR=false: partial g_i @ W1[sec] over K-split -> d_part[z][sec]
//   PAIR=true : (i∘j)@W1c full K + fused MLP epilogue -> d_scores
// A double-buffered (products prefetched in regs), B double-buffered cp.async.
// ---------------------------------------------------------------------------
template<bool PAIR>
__global__ __launch_bounds__(256, 2)
void mma_kernel(const float* __restrict__ G,
                const int*   __restrict__ m_ids,
                const int*   __restrict__ a_ids,
                const int*   __restrict__ spk_lbl,
                const float* __restrict__ mscores,
                const float* __restrict__ W2,
                const float* __restrict__ b2,
                int nchunks) {
    __shared__ float As[2][TM][APAD];      // 20.5 KB
    __shared__ float Bs[2][TK][BPAD];      // 21.5 KB
    __shared__ float srow[4][TM];
    __shared__ float bias_s[3 * TN];
    __shared__ float w2s[TN];

    const int tid = threadIdx.x;
    const int wid = tid >> 5, lane = tid & 31;
    const int gID = lane >> 2, tig = lane & 3;
    const int warp_m = wid & 1, warp_n = wid >> 1;
    const int base = blockIdx.x * TM;
    const int kbc = PAIR ? 0 : blockIdx.z * NCH_PRE;   // chunk offset

    if (PAIR) {
        if (tid < TN) w2s[tid] = (tid < HIDDEN) ? W2[tid] : 0.f;
        for (int i = tid; i < 3 * TN; i += 256) bias_s[i] = d_bias[i];
    }

    const float* Wp = d_Wp + (size_t)(PAIR ? 2 : blockIdx.y) * G_DIM * TN;

    // staging: 2 threads per A row, 8 k each
    const int row = tid >> 1, half = tid & 1;
    const float *rowI, *rowJ = nullptr;
    if (PAIR) {
        int ii = m_ids[base + row], jj = a_ids[base + row];
        rowI = G + (size_t)ii * G_DIM + kbc * TK + half * 8;
        rowJ = G + (size_t)jj * G_DIM + kbc * TK + half * 8;
    } else {
        rowI = G + (size_t)(base + row) * G_DIM + kbc * TK + half * 8;
    }

    float acc[4][5][4];
    #pragma unroll
    for (int a = 0; a < 4; a++)
        #pragma unroll
        for (int b = 0; b < 5; b++)
            #pragma unroll
            for (int c = 0; c < 4; c++) acc[a][b][c] = 0.f;

    const uint32_t bs_base = smem_u32(Bs);
    const uint32_t* Au = reinterpret_cast<const uint32_t*>(As);
    const uint32_t* Bu = reinterpret_cast<const uint32_t*>(Bs);

    // helper lambdas (inlined)
    auto make_prod = [&](int c, float4& p0, float4& p1) {
        const float* pI = rowI + c * TK;
        float4 v0 = *reinterpret_cast<const float4*>(pI);
        float4 v1 = *reinterpret_cast<const float4*>(pI + 4);
        if (PAIR) {
            const float* pJ = rowJ + c * TK;
            float4 u0 = *reinterpret_cast<const float4*>(pJ);
            float4 u1 = *reinterpret_cast<const float4*>(pJ + 4);
            p0.x = __uint_as_float(f2tf32(v0.x * u0.x));
            p0.y = __uint_as_float(f2tf32(v0.y * u0.y));
            p0.z = __uint_as_float(f2tf32(v0.z * u0.z));
            p0.w = __uint_as_float(f2tf32(v0.w * u0.w));
            p1.x = __uint_as_float(f2tf32(v1.x * u1.x));
            p1.y = __uint_as_float(f2tf32(v1.y * u1.y));
            p1.z = __uint_as_float(f2tf32(v1.z * u1.z));
            p1.w = __uint_as_float(f2tf32(v1.w * u1.w));
        } else {
            p0.x = __uint_as_float(f2tf32(v0.x));
            p0.y = __uint_as_float(f2tf32(v0.y));
            p0.z = __uint_as_float(f2tf32(v0.z));
            p0.w = __uint_as_float(f2tf32(v0.w));
            p1.x = __uint_as_float(f2tf32(v1.x));
            p1.y = __uint_as_float(f2tf32(v1.y));
            p1.z = __uint_as_float(f2tf32(v1.z));
            p1.w = __uint_as_float(f2tf32(v1.w));
        }
    };
    auto stage_B = [&](int c, int stg) {
        const float* wsrc = Wp + (size_t)(kbc + c) * TK * TN;
        #pragma unroll
        for (int it = 0; it < 3; it++) {
            int u = tid + it * 256;
            if (u < 640) {
                int k = u / 40, hq = u - k * 40;
                cp_async16(bs_base + (uint32_t)((stg * TK + k) * BPAD + hq * 4) * 4u,
                           wsrc + k * TN + hq * 4);
            }
        }
    };

    // ---- prologue: chunk 0 ----
    {
        stage_B(0, 0);
        asm volatile("cp.async.commit_group;" ::: "memory");
        float4 p0, p1;
        make_prod(0, p0, p1);
        *reinterpret_cast<float4*>(&As[0][row][half * 8]) = p0;
        *reinterpret_cast<float4*>(&As[0][row][half * 8 + 4]) = p1;
        asm volatile("cp.async.wait_group 0;" ::: "memory");
    }

    for (int c = 0; c < nchunks; c++) {
        const int cur = c & 1, nxt = cur ^ 1;
        __syncthreads();
        const bool hasNext = (c + 1 < nchunks);
        if (hasNext) stage_B(c + 1, nxt);
        asm volatile("cp.async.commit_group;" ::: "memory");
        float4 p0, p1;
        if (hasNext) make_prod(c + 1, p0, p1);

        // ---- MMA over buffer cur ----
        #pragma unroll
        for (int ks = 0; ks < 2; ks++) {
            uint32_t af[4][4];
            #pragma unroll
            for (int tm = 0; tm < 4; tm++) {
                int m0 = warp_m * 64 + tm * 16 + gID;
                int b0 = cur * (TM * APAD) + m0 * APAD + ks * 8 + tig;
                af[tm][0] = Au[b0];
                af[tm][1] = Au[b0 + 8 * APAD];
                af[tm][2] = Au[b0 + 4];
                af[tm][3] = Au[b0 + 8 * APAD + 4];
            }
            #pragma unroll
            for (int tn = 0; tn < 5; tn++) {
                int col = warp_n * 40 + tn * 8 + gID;
                uint32_t bf[2];
                int r0 = cur * (TK * BPAD) + (ks * 8 + tig) * BPAD + col;
                bf[0] = Bu[r0];
                bf[1] = Bu[r0 + 4 * BPAD];
                #pragma unroll
                for (int tm = 0; tm < 4; tm++)
                    mma_tf32(acc[tm][tn], af[tm], bf);
            }
        }

        if (hasNext) {
            *reinterpret_cast<float4*>(&As[nxt][row][half * 8]) = p0;
            *reinterpret_cast<float4*>(&As[nxt][row][half * 8 + 4]) = p1;
        }
        asm volatile("cp.async.wait_group 0;" ::: "memory");
    }

    // ---- epilogue ----
    if (PAIR) {
        __syncthreads();
        #pragma unroll
        for (int tm = 0; tm < 4; tm++) {
            #pragma unroll
            for (int rh = 0; rh < 2; rh++) {
                const int lr = warp_m * 64 + tm * 16 + rh * 8 + gID;
                const int p = base + lr;
                const int ii = m_ids[p], jj = a_ids[p], sp = spk_lbl[p];
                const float* Ar = d_Abuf + (size_t)ii * TN;
                const float* Br = d_Bbuf + (size_t)jj * TN;
                const float* bi = bias_s + sp * TN;
                float part = 0.f;
                #pragma unroll
                for (int tn = 0; tn < 5; tn++) {
                    const int h = warp_n * 40 + tn * 8 + tig * 2;
                    float2 av = *reinterpret_cast<const float2*>(Ar + h);
                    float2 bv = *reinterpret_cast<const float2*>(Br + h);
                    float v0 = acc[tm][tn][rh * 2 + 0] + av.x + bv.x + bi[h];
                    float v1 = acc[tm][tn][rh * 2 + 1] + av.y + bv.y + bi[h + 1];
                    part = fmaf(fmaxf(v0, 0.f), w2s[h], part);
                    part = fmaf(fmaxf(v1, 0.f), w2s[h + 1], part);
                }
                part += __shfl_xor_sync(0xffffffffu, part, 1);
                part += __shfl_xor_sync(0xffffffffu, part, 2);
                if (tig == 0) srow[warp_n][lr] = part;
            }
        }
        __syncthreads();
        if (tid < TM) {
            const int p = base + tid;
            d_scores[p] = srow[0][tid] + srow[1][tid] + srow[2][tid] + srow[3][tid]
                        + b2[0] + mscores[m_ids[p]] + mscores[a_ids[p]];
        }
    } else {
        float* out = &d_part[blockIdx.z][blockIdx.y][0];
        #pragma unroll
        for (int tm = 0; tm < 4; tm++) {
            #pragma unroll
            for (int rh = 0; rh < 2; rh++) {
                const int m = base + warp_m * 64 + tm * 16 + rh * 8 + gID;
                #pragma unroll
                for (int tn = 0; tn < 5; tn++) {
                    const int h = warp_n * 40 + tn * 8 + tig * 2;
                    float2 v = make_float2(acc[tm][tn][rh * 2 + 0],
                                           acc[tm][tn][rh * 2 + 1]);
                    *reinterpret_cast<float2*>(out + (size_t)m * TN + h) = v;
                }
            }
        }
    }
}

// ---------------------------------------------------------------------------
// Sum the K-split partials (fixed order -> deterministic).
// ---------------------------------------------------------------------------
__global__ void combine_kernel() {
    const int TOT = 2 * N_MENT * TN / 4;   // float4 units per split
    int q = blockIdx.x * 256 + threadIdx.x;
    if (q >= TOT) return;
    const float4* p = reinterpret_cast<const float4*>(d_part);
    float4 a = p[q], b = p[q + TOT], c = p[q + 2 * TOT], d = p[q + 3 * TOT];
    float4 r;
    r.x = a.x + b.x + c.x + d.x;
    r.y = a.y + b.y + c.y + d.y;
    r.z = a.z + b.z + c.z + d.z;
    r.w = a.w + b.w + c.w + d.w;
    const int HALF = TOT / 2;
    if (q < HALF) reinterpret_cast<float4*>(d_Abuf)[q] = r;
    else          reinterpret_cast<float4*>(d_Bbuf)[q - HALF] = r;
}

// ---------------------------------------------------------------------------
// Ragged softmax, one warp per segment (sorted segment_ids).
// ---------------------------------------------------------------------------
__global__ void softmax_kernel(const int* __restrict__ seg_ids,
                               float* __restrict__ out) {
    const int s = (blockIdx.x * blockDim.x + threadIdx.x) >> 5;
    const int lane = threadIdx.x & 31;
    if (s >= N_SEG) return;

    int lo = 0, hi = N_PAIRS;
    while (lo < hi) { int mid = (lo + hi) >> 1; if (seg_ids[mid] < s) lo = mid + 1; else hi = mid; }
    const int start = lo;
    hi = N_PAIRS;
    while (lo < hi) { int mid = (lo + hi) >> 1; if (seg_ids[mid] <= s) lo = mid + 1; else hi = mid; }
    const int end = lo;

    float m = 0.f;
    for (int p = start + lane; p < end; p += 32) m = fmaxf(m, d_scores[p]);
    #pragma unroll
    for (int o = 16; o; o >>= 1) m = fmaxf(m, __shfl_xor_sync(0xffffffffu, m, o));

    float sum = 0.f;
    for (int p = start + lane; p < end; p += 32) sum += expf(d_scores[p] - m);
    #pragma unroll
    for (int o = 16; o; o >>= 1) sum += __shfl_xor_sync(0xffffffffu, sum, o);

    const float eps_e = expf(-m);
    const float inv = 1.f / (sum + eps_e);
    for (int p = start + lane; p < end; p += 32)
        out[p] = expf(d_scores[p] - m) * inv;
    if (lane == 0) out[N_PAIRS + s] = eps_e * inv;
}

// ---------------------------------------------------------------------------
extern "C" void kernel_launch(void* const* d_in, const int* in_sizes, int n_in,
                              void* d_out, int out_size) {
    const float* g_i            = (const float*)d_in[0];
    const float* mention_scores = (const float*)d_in[1];
    const float* speaker_embed  = (const float*)d_in[2];
    const float* W1             = (const float*)d_in[3];
    const float* b1             = (const float*)d_in[4];
    const float* W2             = (const float*)d_in[5];
    const float* b2             = (const float*)d_in[6];
    const int*   mention_ids    = (const int*)d_in[7];
    const int*   antecedent_ids = (const int*)d_in[8];
    const int*   speaker_labels = (const int*)d_in[9];
    const int*   segment_ids    = (const int*)d_in[10];
    float* out = (float*)d_out;

    prep_w_kernel<<<(3 * G_DIM * TN + 255) / 256, 256>>>(W1);
    bias_kernel<<<1, 256>>>(speaker_embed, W1, b1);
    // precompute: 32 M-tiles x 2 sections x 4 K-splits = 256 CTAs (full wave)
    mma_kernel<false><<<dim3(N_MENT / TM, 2, KSPLIT), 256>>>(
        g_i, mention_ids, antecedent_ids, speaker_labels, mention_scores,
        W2, b2, NCH_PRE);
    combine_kernel<<<(2 * N_MENT * TN / 4 + 255) / 256, 256>>>();
    // pair bilinear + fused epilogue: 256 CTAs
    mma_kernel<true><<<dim3(N_PAIRS / TM, 1, 1), 256>>>(
        g_i, mention_ids, antecedent_ids, speaker_labels, mention_scores,
        W2, b2, NCH_ALL);
    softmax_kernel<<<(N_SEG * 32 + 255) / 256, 256>>>(segment_ids, out);
}